// round 5
// baseline (speedup 1.0000x reference)
#include <cuda_runtime.h>
#include <cstdint>

#define BB   32
#define SS   1024
#define HH   256
#define G4   1024   // 4*H
#define H2   512    // 2*H

// ------------------------- scratch (device globals; no allocs) -------------
__device__ float g_gates_f[(size_t)SS * BB * G4];   // 128 MB
__device__ float g_gates_b[(size_t)SS * BB * G4];   // 128 MB
__device__ float g_xout  [(size_t)SS * BB * H2];    //  64 MB (layer-0 output)
__device__ int   g_flags [2 * 2 * SS];              // [layer][dir][step]

// --------------------------------------------------------------------------
__global__ void zero_flags_k()
{
    int i = blockIdx.x * blockDim.x + threadIdx.x;
    if (i < 2 * 2 * SS) g_flags[i] = 0;
}

// --------------------------------------------------------------------------
// C[m, n] = sum_k A_row(m)[k] * W[n, k] + bih[n] + bhh[n]
// m = s*B + b.  a_mode 0: A indexed as inputs[b][s][k]; a_mode 1: row-major m*K.
// Tiles 128x128, k-tile 16, 256 threads, 8x8 micro-tile.
__global__ void __launch_bounds__(256) gates_gemm(
    const float* __restrict__ A, const float* __restrict__ W,
    const float* __restrict__ bih, const float* __restrict__ bhh,
    float* __restrict__ C, int K, int a_mode)
{
    __shared__ float As[16][132];
    __shared__ float Bs[16][132];

    const int tid = threadIdx.x;
    const int tx = tid & 15;
    const int ty = tid >> 4;
    const int m0 = blockIdx.y * 128;
    const int n0 = blockIdx.x * 128;

    const int lr = tid >> 2;        // 0..63
    const int lc = (tid & 3) << 2;  // 0,4,8,12

    const float* arow0;
    const float* arow1;
    {
        int m  = m0 + lr;
        int m2 = m + 64;
        if (a_mode == 0) {
            int s = m >> 5, b = m & 31;
            arow0 = A + ((size_t)b * SS + s) * K;
            s = m2 >> 5; b = m2 & 31;
            arow1 = A + ((size_t)b * SS + s) * K;
        } else {
            arow0 = A + (size_t)m  * K;
            arow1 = A + (size_t)m2 * K;
        }
    }
    const float* wrow0 = W + (size_t)(n0 + lr)      * K;
    const float* wrow1 = W + (size_t)(n0 + lr + 64) * K;

    float acc[8][8];
#pragma unroll
    for (int i = 0; i < 8; ++i)
#pragma unroll
        for (int j = 0; j < 8; ++j) acc[i][j] = 0.f;

    for (int k0 = 0; k0 < K; k0 += 16) {
        float4 a0 = *(const float4*)(arow0 + k0 + lc);
        float4 a1 = *(const float4*)(arow1 + k0 + lc);
        float4 b0 = *(const float4*)(wrow0 + k0 + lc);
        float4 b1 = *(const float4*)(wrow1 + k0 + lc);
        __syncthreads();
        As[lc + 0][lr] = a0.x; As[lc + 1][lr] = a0.y; As[lc + 2][lr] = a0.z; As[lc + 3][lr] = a0.w;
        As[lc + 0][lr + 64] = a1.x; As[lc + 1][lr + 64] = a1.y; As[lc + 2][lr + 64] = a1.z; As[lc + 3][lr + 64] = a1.w;
        Bs[lc + 0][lr] = b0.x; Bs[lc + 1][lr] = b0.y; Bs[lc + 2][lr] = b0.z; Bs[lc + 3][lr] = b0.w;
        Bs[lc + 0][lr + 64] = b1.x; Bs[lc + 1][lr + 64] = b1.y; Bs[lc + 2][lr + 64] = b1.z; Bs[lc + 3][lr + 64] = b1.w;
        __syncthreads();
#pragma unroll
        for (int k = 0; k < 16; ++k) {
            float4 af0 = *(const float4*)&As[k][ty * 4];
            float4 af1 = *(const float4*)&As[k][64 + ty * 4];
            float4 bf0 = *(const float4*)&Bs[k][tx * 4];
            float4 bf1 = *(const float4*)&Bs[k][64 + tx * 4];
            float a_[8] = {af0.x, af0.y, af0.z, af0.w, af1.x, af1.y, af1.z, af1.w};
            float b_[8] = {bf0.x, bf0.y, bf0.z, bf0.w, bf1.x, bf1.y, bf1.z, bf1.w};
#pragma unroll
            for (int i = 0; i < 8; ++i)
#pragma unroll
                for (int j = 0; j < 8; ++j)
                    acc[i][j] += a_[i] * b_[j];
        }
    }

#pragma unroll
    for (int qi = 0; qi < 2; ++qi) {
#pragma unroll
        for (int i = 0; i < 4; ++i) {
            int m = m0 + qi * 64 + ty * 4 + i;
            float* crow = C + (size_t)m * G4 + n0;
#pragma unroll
            for (int qj = 0; qj < 2; ++qj) {
                int nb = qj * 64 + tx * 4;
                float4 v;
                v.x = acc[qi * 4 + i][qj * 4 + 0] + bih[n0 + nb + 0] + bhh[n0 + nb + 0];
                v.y = acc[qi * 4 + i][qj * 4 + 1] + bih[n0 + nb + 1] + bhh[n0 + nb + 1];
                v.z = acc[qi * 4 + i][qj * 4 + 2] + bih[n0 + nb + 2] + bhh[n0 + nb + 2];
                v.w = acc[qi * 4 + i][qj * 4 + 3] + bih[n0 + nb + 3] + bhh[n0 + nb + 3];
                *(float4*)(crow + nb) = v;
            }
        }
    }
}

// --------------------------------------------------------------------------
// Recurrence: 128 CTAs (blockIdx < 64: forward, else backward), 256 threads.
// Each CTA owns 4 hidden units -> 16 gate rows of Whh.
// Per-step cross-CTA sync via a counter in global memory (release: fence +
// atomicAdd; acquire: volatile poll + fence).
// out_bs == 0: h tensor indexed [S, B, 2H]; out_bs == 1: [B, S, 2H].
#define NCTA_PER_DIR 64
#define HS 260          // padded shared strides (bank-conflict free, 16B aligned)
#define GS 17

__global__ void __launch_bounds__(256) lstm_recur(
    const float* __restrict__ gatesF, const float* __restrict__ gatesB,
    const float* __restrict__ WhhF, const float* __restrict__ WhhB,
    const float* __restrict__ mask,
    float* __restrict__ xout,
    float* __restrict__ hn_out, float* __restrict__ cn_out,
    int* __restrict__ flags, int out_bs)
{
    extern __shared__ float sm[];
    float* sh_w = sm;                       // 16 * HS
    float* sh_h = sm + 16 * HS;             // 32 * HS
    float* sh_g = sm + 16 * HS + 32 * HS;   // 32 * GS

    const int tid = threadIdx.x;
    const int dir = blockIdx.x >> 6;
    const int cb  = blockIdx.x & 63;
    const int u0  = cb * 4;

    const float* gates = dir ? gatesB : gatesF;
    const float* Whh   = dir ? WhhB   : WhhF;
    int* fl = flags + dir * SS;

    // Load the 16 Whh rows for this CTA's units: lr = gate*4 + uu
    for (int idx = tid; idx < 16 * 64; idx += 256) {
        int lrr = idx >> 6;
        int k4  = idx & 63;
        int grow = (lrr >> 2) * HH + u0 + (lrr & 3);
        float4 v = *(const float4*)(Whh + (size_t)grow * HH + k4 * 4);
        *(float4*)&sh_w[lrr * HS + k4 * 4] = v;
    }

    const int gb = tid >> 3;      // batch row this thread multiplies
    const int gi = tid & 7;
    const int r0 = gi, r1 = gi + 8;
    const int col0 = (r0 >> 2) * HH + u0 + (r0 & 3);
    const int col1 = (r1 >> 2) * HH + u0 + (r1 & 3);

    const int cu   = tid >> 5;    // cell threads (tid<128): unit 0..3
    const int cbat = tid & 31;    //                          batch 0..31
    float c_state = 0.f;

    __syncthreads();

    for (int t = 0; t < SS; ++t) {
        const int s = dir ? (SS - 1 - t) : t;

        // precomputed x-gates for this step (issue early, long-latency)
        const float* gx = gates + ((size_t)s * BB + gb) * G4;
        float acc0 = gx[col0];
        float acc1 = gx[col1];

        if (t == 0) {
            for (int idx = tid; idx < 32 * HS; idx += 256) sh_h[idx] = 0.f;
        } else {
            if (tid == 0) {
                volatile int* p = fl + (t - 1);
                while (*p < NCTA_PER_DIR) { __nanosleep(32); }
            }
            __syncthreads();
            __threadfence();   // acquire before reading peers' h
            const int sprev = dir ? (s + 1) : (s - 1);
            for (int q = tid; q < 32 * 64; q += 256) {
                int b = q >> 6, k4 = q & 63;
                size_t row = out_bs ? ((size_t)b * SS + sprev)
                                    : ((size_t)sprev * BB + b);
                float4 v = *(const float4*)(xout + row * H2 + dir * HH + k4 * 4);
                *(float4*)&sh_h[b * HS + k4 * 4] = v;
            }
        }
        __syncthreads();

        // gates_h = h_prev @ Whh_slice^T   (2 outputs per thread)
        const float* hrow = &sh_h[gb * HS];
        const float* w0 = &sh_w[r0 * HS];
        const float* w1 = &sh_w[r1 * HS];
#pragma unroll 16
        for (int k4 = 0; k4 < 64; ++k4) {
            float4 hv  = *(const float4*)(hrow + k4 * 4);
            float4 wv0 = *(const float4*)(w0 + k4 * 4);
            float4 wv1 = *(const float4*)(w1 + k4 * 4);
            acc0 += hv.x * wv0.x; acc0 += hv.y * wv0.y;
            acc0 += hv.z * wv0.z; acc0 += hv.w * wv0.w;
            acc1 += hv.x * wv1.x; acc1 += hv.y * wv1.y;
            acc1 += hv.z * wv1.z; acc1 += hv.w * wv1.w;
        }
        sh_g[gb * GS + r0] = acc0;
        sh_g[gb * GS + r1] = acc1;
        __syncthreads();

        if (tid < 128) {
            float gI = sh_g[cbat * GS + 0  + cu];
            float gF = sh_g[cbat * GS + 4  + cu];
            float gG = sh_g[cbat * GS + 8  + cu];
            float gO = sh_g[cbat * GS + 12 + cu];
            float ig = 1.f / (1.f + expf(-gI));
            float fg = 1.f / (1.f + expf(-gF));
            float gg = tanhf(gG);
            float og = 1.f / (1.f + expf(-gO));
            float cn = fg * c_state + ig * gg;
            float hn = og * tanhf(cn);
            float mt = mask[cbat * SS + s];
            hn *= mt;                  // + h0*(1-mt), h0 == 0
            cn *= mt;                  // + c0*(1-mt), c0 == 0
            c_state = cn;
            size_t orow = out_bs ? ((size_t)cbat * SS + s)
                                 : ((size_t)s * BB + cbat);
            xout[orow * H2 + dir * HH + u0 + cu] = hn;
            if (t == SS - 1) {
                hn_out[cbat * H2 + dir * HH + u0 + cu] = hn;
                cn_out[cbat * H2 + dir * HH + u0 + cu] = cn;
            }
        }
        __threadfence();   // release our h writes
        __syncthreads();
        if (tid == 0) atomicAdd(fl + t, 1);
    }
}

// --------------------------------------------------------------------------
extern "C" void kernel_launch(void* const* d_in, const int* in_sizes, int n_in,
                              void* d_out, int out_size)
{
    const float* inputs  = (const float*)d_in[0];
    const float* mask    = (const float*)d_in[1];
    const float* l0f_Wih = (const float*)d_in[2];
    const float* l0f_Whh = (const float*)d_in[3];
    const float* l0f_bih = (const float*)d_in[4];
    const float* l0f_bhh = (const float*)d_in[5];
    const float* l0b_Wih = (const float*)d_in[6];
    const float* l0b_Whh = (const float*)d_in[7];
    const float* l0b_bih = (const float*)d_in[8];
    const float* l0b_bhh = (const float*)d_in[9];
    const float* l1f_Wih = (const float*)d_in[10];
    const float* l1f_Whh = (const float*)d_in[11];
    const float* l1f_bih = (const float*)d_in[12];
    const float* l1f_bhh = (const float*)d_in[13];
    const float* l1b_Wih = (const float*)d_in[14];
    const float* l1b_Whh = (const float*)d_in[15];
    const float* l1b_bih = (const float*)d_in[16];
    const float* l1b_bhh = (const float*)d_in[17];
    float* out = (float*)d_out;

    float *p_gf, *p_gb, *p_x;
    int *p_fl;
    cudaGetSymbolAddress((void**)&p_gf, g_gates_f);
    cudaGetSymbolAddress((void**)&p_gb, g_gates_b);
    cudaGetSymbolAddress((void**)&p_x,  g_xout);
    cudaGetSymbolAddress((void**)&p_fl, g_flags);

    const int smem_rec = (16 * HS + 32 * HS + 32 * GS) * 4;   // 52096 B
    cudaFuncSetAttribute(lstm_recur, cudaFuncAttributeMaxDynamicSharedMemorySize, smem_rec);

    const size_t HN_OFF = (size_t)BB * SS * H2;       // 16777216
    const size_t CN_OFF = HN_OFF + 2 * (size_t)BB * H2;
    float* hn0 = out + HN_OFF;
    float* hn1 = out + HN_OFF + (size_t)BB * H2;
    float* cn0 = out + CN_OFF;
    float* cn1 = out + CN_OFF + (size_t)BB * H2;

    zero_flags_k<<<16, 256>>>();

    dim3 ggrid(G4 / 128, (SS * BB) / 128);   // (8, 256)

    // ---- layer 0 : recurrence output in [S,B,2H] scratch ----
    gates_gemm<<<ggrid, 256>>>(inputs, l0f_Wih, l0f_bih, l0f_bhh, p_gf, 256, 0);
    gates_gemm<<<ggrid, 256>>>(inputs, l0b_Wih, l0b_bih, l0b_bhh, p_gb, 256, 0);
    lstm_recur<<<128, 256, smem_rec>>>(p_gf, p_gb, l0f_Whh, l0b_Whh, mask,
                                       p_x, hn0, cn0, p_fl, 0);

    // ---- layer 1 : recurrence writes final [B,S,2H] output directly ----
    gates_gemm<<<ggrid, 256>>>(p_x, l1f_Wih, l1f_bih, l1f_bhh, p_gf, 512, 1);
    gates_gemm<<<ggrid, 256>>>(p_x, l1b_Wih, l1b_bih, l1b_bhh, p_gb, 512, 1);
    lstm_recur<<<128, 256, smem_rec>>>(p_gf, p_gb, l1f_Whh, l1b_Whh, mask,
                                       out, hn1, cn1, p_fl + 2 * SS, 1);
}

// round 6
// speedup vs baseline: 1.0332x; 1.0332x over previous
#include <cuda_runtime.h>
#include <cstdint>

#define BB   32
#define SS   1024
#define HH   256
#define G4   1024   // 4*H
#define H2   512    // 2*H

typedef unsigned long long ull;

// ---------------- f32x2 helpers (Blackwell packed fp32, 2 MAC/inst) -------
__device__ __forceinline__ ull ffma2(ull a, ull b, ull c)
{
    ull d;
    asm("fma.rn.f32x2 %0, %1, %2, %3;" : "=l"(d) : "l"(a), "l"(b), "l"(c));
    return d;
}
__device__ __forceinline__ ull pack_dup(float a)
{
    ull d;
    unsigned u = __float_as_uint(a);
    asm("mov.b64 %0, {%1, %1};" : "=l"(d) : "r"(u));
    return d;
}
__device__ __forceinline__ float2 unpack2(ull v)
{
    unsigned lo, hi;
    asm("mov.b64 {%0, %1}, %2;" : "=r"(lo), "=r"(hi) : "l"(v));
    return make_float2(__uint_as_float(lo), __uint_as_float(hi));
}

// ------------------------- scratch (device globals; no allocs) -------------
// gates in recurrence layout: [s][unit_block(64)][b(32)][16]  (16 = gate*4+u)
__device__ float g_gates_f[(size_t)SS * BB * G4];   // 128 MB
__device__ float g_gates_b[(size_t)SS * BB * G4];   // 128 MB
__device__ float g_xout  [(size_t)SS * BB * H2];    //  64 MB (layer-0 output)
__device__ int   g_flags [2 * 2 * 64];              // [layer][dir][producer]

// --------------------------------------------------------------------------
__global__ void zero_flags_k()
{
    int i = threadIdx.x;
    if (i < 2 * 2 * 64) g_flags[i] = 0;
}

// --------------------------------------------------------------------------
// gates2[s][ub][b][g*4+u] = sum_k A_row(s,b)[k] * W[g*256+ub*4+u, k] + bih + bhh
// m = s*B + b.  a_mode 0: A indexed as inputs[b][s][k]; a_mode 1: row-major m*K.
// Tiles 128x128, k-tile 16, 256 threads, 8x8 micro-tile, f32x2 math.
__global__ void __launch_bounds__(256) gates_gemm(
    const float* __restrict__ A, const float* __restrict__ W,
    const float* __restrict__ bih, const float* __restrict__ bhh,
    float* __restrict__ C2, int K, int a_mode)
{
    __shared__ __align__(16) float As[16][132];
    __shared__ __align__(16) float Bs[16][132];

    const int tid = threadIdx.x;
    const int tx = tid & 15;
    const int ty = tid >> 4;
    const int m0 = blockIdx.y * 128;
    const int n0 = blockIdx.x * 128;

    const int lr = tid >> 2;        // 0..63
    const int lc = (tid & 3) << 2;  // 0,4,8,12

    const float* arow0;
    const float* arow1;
    {
        int m  = m0 + lr;
        int m2 = m + 64;
        if (a_mode == 0) {
            int s = m >> 5, b = m & 31;
            arow0 = A + ((size_t)b * SS + s) * K;
            s = m2 >> 5; b = m2 & 31;
            arow1 = A + ((size_t)b * SS + s) * K;
        } else {
            arow0 = A + (size_t)m  * K;
            arow1 = A + (size_t)m2 * K;
        }
    }
    const float* wrow0 = W + (size_t)(n0 + lr)      * K;
    const float* wrow1 = W + (size_t)(n0 + lr + 64) * K;

    // accp[i][j]: packed pair of output cols; j 0..1 -> cols tx*4+{0,1},{2,3};
    //             j 2..3 -> cols 64+tx*4+{0,1},{2,3}
    ull accp[8][4];
#pragma unroll
    for (int i = 0; i < 8; ++i)
#pragma unroll
        for (int j = 0; j < 4; ++j) accp[i][j] = 0ull;

    for (int k0 = 0; k0 < K; k0 += 16) {
        float4 a0 = *(const float4*)(arow0 + k0 + lc);
        float4 a1 = *(const float4*)(arow1 + k0 + lc);
        float4 b0 = *(const float4*)(wrow0 + k0 + lc);
        float4 b1 = *(const float4*)(wrow1 + k0 + lc);
        __syncthreads();
        As[lc + 0][lr] = a0.x; As[lc + 1][lr] = a0.y; As[lc + 2][lr] = a0.z; As[lc + 3][lr] = a0.w;
        As[lc + 0][lr + 64] = a1.x; As[lc + 1][lr + 64] = a1.y; As[lc + 2][lr + 64] = a1.z; As[lc + 3][lr + 64] = a1.w;
        Bs[lc + 0][lr] = b0.x; Bs[lc + 1][lr] = b0.y; Bs[lc + 2][lr] = b0.z; Bs[lc + 3][lr] = b0.w;
        Bs[lc + 0][lr + 64] = b1.x; Bs[lc + 1][lr + 64] = b1.y; Bs[lc + 2][lr + 64] = b1.z; Bs[lc + 3][lr + 64] = b1.w;
        __syncthreads();
#pragma unroll
        for (int k = 0; k < 16; ++k) {
            float4 af0 = *(const float4*)&As[k][ty * 4];
            float4 af1 = *(const float4*)&As[k][64 + ty * 4];
            ulonglong2 bv0 = *(const ulonglong2*)&Bs[k][tx * 4];
            ulonglong2 bv1 = *(const ulonglong2*)&Bs[k][64 + tx * 4];
            ull bp[4] = {bv0.x, bv0.y, bv1.x, bv1.y};
            float a_[8] = {af0.x, af0.y, af0.z, af0.w, af1.x, af1.y, af1.z, af1.w};
#pragma unroll
            for (int i = 0; i < 8; ++i) {
                ull ad = pack_dup(a_[i]);
#pragma unroll
                for (int j = 0; j < 4; ++j)
                    accp[i][j] = ffma2(ad, bp[j], accp[i][j]);
            }
        }
    }

    // epilogue: bias add + store in recurrence layout
#pragma unroll
    for (int qi = 0; qi < 2; ++qi) {
#pragma unroll
        for (int i = 0; i < 4; ++i) {
            int m = m0 + qi * 64 + ty * 4 + i;
            int s = m >> 5, b = m & 31;
#pragma unroll
            for (int qj = 0; qj < 2; ++qj) {
                int n = n0 + qj * 64 + tx * 4;
                float2 p0 = unpack2(accp[qi * 4 + i][qj * 2 + 0]);
                float2 p1 = unpack2(accp[qi * 4 + i][qj * 2 + 1]);
                float4 v;
                v.x = p0.x + bih[n + 0] + bhh[n + 0];
                v.y = p0.y + bih[n + 1] + bhh[n + 1];
                v.z = p1.x + bih[n + 2] + bhh[n + 2];
                v.w = p1.y + bih[n + 3] + bhh[n + 3];
                int g  = n >> 8;
                int ub = (n & 255) >> 2;
                *(float4*)&C2[(((size_t)s * 64 + ub) * 32 + b) * 16 + g * 4] = v;
            }
        }
    }
}

// --------------------------------------------------------------------------
// Recurrence: 128 CTAs (blockIdx < 64: forward, else backward), 256 threads.
// Each CTA owns 4 hidden units -> 16 gate rows of Whh.
// Per-step cross-CTA sync: per-producer flag word (value = steps completed);
// release = threadfence + volatile store; acquire = 64-thread parallel poll
// + threadfence.
// out_bs == 0: h tensor indexed [S, B, 2H]; out_bs == 1: [B, S, 2H].
#define HS 260          // padded shared strides (bank-conflict free, 16B aligned)
#define GS 17

__device__ __forceinline__ float sigm_f(float x)
{
    float e = __expf(-x);
    return __fdividef(1.f, 1.f + e);
}
__device__ __forceinline__ float tanh_f(float x)
{
    float xc = fminf(fmaxf(x, -30.f), 30.f);
    float e = __expf(-2.f * xc);
    return __fdividef(1.f - e, 1.f + e);
}

__global__ void __launch_bounds__(256) lstm_recur(
    const float* __restrict__ gatesF2, const float* __restrict__ gatesB2,
    const float* __restrict__ WhhF, const float* __restrict__ WhhB,
    const float* __restrict__ mask,
    float* __restrict__ xout,
    float* __restrict__ hn_out, float* __restrict__ cn_out,
    int* __restrict__ flags, int out_bs)
{
    extern __shared__ __align__(16) float sm[];
    float* sh_w = sm;                       // 16 * HS
    float* sh_h = sm + 16 * HS;             // 32 * HS
    float* sh_g = sm + 16 * HS + 32 * HS;   // 32 * GS

    const int tid = threadIdx.x;
    const int dir = blockIdx.x >> 6;
    const int cb  = blockIdx.x & 63;
    const int u0  = cb * 4;

    const float* gates2 = dir ? gatesB2 : gatesF2;
    const float* Whh    = dir ? WhhB    : WhhF;
    int* fl = flags + dir * 64;
    volatile int* flv = fl;

    // Load the 16 Whh rows for this CTA's units: row r = gate*4 + u
    for (int idx = tid; idx < 16 * 64; idx += 256) {
        int r  = idx >> 6;
        int k4 = idx & 63;
        int grow = (r >> 2) * HH + u0 + (r & 3);
        float4 v = *(const float4*)(Whh + (size_t)grow * HH + k4 * 4);
        *(float4*)&sh_w[r * HS + k4 * 4] = v;
    }

    const int gb = tid >> 3;      // batch row this thread multiplies
    const int gi = tid & 7;
    const int r0 = gi, r1 = gi + 8;

    const int cu   = tid >> 5;    // cell threads (tid<128): unit 0..3
    const int cbat = tid & 31;    //                          batch 0..31
    float c_state = 0.f;

    __syncthreads();

    for (int t = 0; t < SS; ++t) {
        const int s = dir ? (SS - 1 - t) : t;

        // precomputed x-gates: contiguous 2 KB per (step, CTA); issue early
        const float* gr = gates2 + ((size_t)s * 64 + cb) * 512 + gb * 16;
        float gx0 = gr[r0];
        float gx1 = gr[r1];

        if (t == 0) {
            for (int idx = tid; idx < 32 * HS; idx += 256) sh_h[idx] = 0.f;
        } else {
            if (tid < 64) {
                while (flv[tid] < t) { }
            }
            __syncthreads();
            __threadfence();   // acquire before reading peers' h
            const int sprev = dir ? (s + 1) : (s - 1);
            for (int q = tid; q < 32 * 64; q += 256) {
                int b = q >> 6, k4 = q & 63;
                size_t row = out_bs ? ((size_t)b * SS + sprev)
                                    : ((size_t)sprev * BB + b);
                float4 v = *(const float4*)(xout + row * H2 + dir * HH + k4 * 4);
                *(float4*)&sh_h[b * HS + k4 * 4] = v;
            }
        }
        __syncthreads();

        // gates_h = h_prev @ Whh_slice^T, f32x2 packed over k, 4 chains
        {
            const ulonglong2* hv  = (const ulonglong2*)&sh_h[gb * HS];
            const ulonglong2* w0v = (const ulonglong2*)&sh_w[r0 * HS];
            const ulonglong2* w1v = (const ulonglong2*)&sh_w[r1 * HS];
            ull a0a = 0, a0b = 0, a1a = 0, a1b = 0;
#pragma unroll 16
            for (int k2 = 0; k2 < 64; ++k2) {
                ulonglong2 h = hv[k2];
                ulonglong2 W0 = w0v[k2];
                ulonglong2 W1 = w1v[k2];
                a0a = ffma2(h.x, W0.x, a0a);
                a0b = ffma2(h.y, W0.y, a0b);
                a1a = ffma2(h.x, W1.x, a1a);
                a1b = ffma2(h.y, W1.y, a1b);
            }
            float2 u0a = unpack2(a0a), u0b = unpack2(a0b);
            float2 u1a = unpack2(a1a), u1b = unpack2(a1b);
            sh_g[gb * GS + r0] = gx0 + (u0a.x + u0a.y) + (u0b.x + u0b.y);
            sh_g[gb * GS + r1] = gx1 + (u1a.x + u1a.y) + (u1b.x + u1b.y);
        }
        __syncthreads();

        if (tid < 128) {
            float gI = sh_g[cbat * GS + 0  + cu];
            float gF = sh_g[cbat * GS + 4  + cu];
            float gG = sh_g[cbat * GS + 8  + cu];
            float gO = sh_g[cbat * GS + 12 + cu];
            float ig = sigm_f(gI);
            float fg = sigm_f(gF);
            float gg = tanh_f(gG);
            float og = sigm_f(gO);
            float cn = fg * c_state + ig * gg;
            float hn = og * tanh_f(cn);
            float mt = mask[cbat * SS + s];
            hn *= mt;                  // + h0*(1-mt), h0 == 0
            cn *= mt;                  // + c0*(1-mt), c0 == 0
            c_state = cn;
            size_t orow = out_bs ? ((size_t)cbat * SS + s)
                                 : ((size_t)s * BB + cbat);
            xout[orow * H2 + dir * HH + u0 + cu] = hn;
            if (t == SS - 1) {
                hn_out[cbat * H2 + dir * HH + u0 + cu] = hn;
                cn_out[cbat * H2 + dir * HH + u0 + cu] = cn;
            }
        }
        __threadfence();   // release our h writes (each storer fences itself)
        __syncthreads();   // all stores+fences happen-before the flag store
        if (tid == 0) flv[cb] = t + 1;
    }
}

// --------------------------------------------------------------------------
extern "C" void kernel_launch(void* const* d_in, const int* in_sizes, int n_in,
                              void* d_out, int out_size)
{
    const float* inputs  = (const float*)d_in[0];
    const float* mask    = (const float*)d_in[1];
    const float* l0f_Wih = (const float*)d_in[2];
    const float* l0f_Whh = (const float*)d_in[3];
    const float* l0f_bih = (const float*)d_in[4];
    const float* l0f_bhh = (const float*)d_in[5];
    const float* l0b_Wih = (const float*)d_in[6];
    const float* l0b_Whh = (const float*)d_in[7];
    const float* l0b_bih = (const float*)d_in[8];
    const float* l0b_bhh = (const float*)d_in[9];
    const float* l1f_Wih = (const float*)d_in[10];
    const float* l1f_Whh = (const float*)d_in[11];
    const float* l1f_bih = (const float*)d_in[12];
    const float* l1f_bhh = (const float*)d_in[13];
    const float* l1b_Wih = (const float*)d_in[14];
    const float* l1b_Whh = (const float*)d_in[15];
    const float* l1b_bih = (const float*)d_in[16];
    const float* l1b_bhh = (const float*)d_in[17];
    float* out = (float*)d_out;

    float *p_gf, *p_gb, *p_x;
    int *p_fl;
    cudaGetSymbolAddress((void**)&p_gf, g_gates_f);
    cudaGetSymbolAddress((void**)&p_gb, g_gates_b);
    cudaGetSymbolAddress((void**)&p_x,  g_xout);
    cudaGetSymbolAddress((void**)&p_fl, g_flags);

    const int smem_rec = (16 * HS + 32 * HS + 32 * GS) * 4;   // 52096 B
    cudaFuncSetAttribute(lstm_recur, cudaFuncAttributeMaxDynamicSharedMemorySize, smem_rec);

    const size_t HN_OFF = (size_t)BB * SS * H2;       // 16777216
    const size_t CN_OFF = HN_OFF + 2 * (size_t)BB * H2;
    float* hn0 = out + HN_OFF;
    float* hn1 = out + HN_OFF + (size_t)BB * H2;
    float* cn0 = out + CN_OFF;
    float* cn1 = out + CN_OFF + (size_t)BB * H2;

    zero_flags_k<<<1, 256>>>();

    dim3 ggrid(G4 / 128, (SS * BB) / 128);   // (8, 256)

    // ---- layer 0 : recurrence output in [S,B,2H] scratch ----
    gates_gemm<<<ggrid, 256>>>(inputs, l0f_Wih, l0f_bih, l0f_bhh, p_gf, 256, 0);
    gates_gemm<<<ggrid, 256>>>(inputs, l0b_Wih, l0b_bih, l0b_bhh, p_gb, 256, 0);
    lstm_recur<<<128, 256, smem_rec>>>(p_gf, p_gb, l0f_Whh, l0b_Whh, mask,
                                       p_x, hn0, cn0, p_fl, 0);

    // ---- layer 1 : recurrence writes final [B,S,2H] output directly ----
    gates_gemm<<<ggrid, 256>>>(p_x, l1f_Wih, l1f_bih, l1f_bhh, p_gf, 512, 1);
    gates_gemm<<<ggrid, 256>>>(p_x, l1b_Wih, l1b_bih, l1b_bhh, p_gb, 512, 1);
    lstm_recur<<<128, 256, smem_rec>>>(p_gf, p_gb, l1f_Whh, l1b_Whh, mask,
                                       out, hn1, cn1, p_fl + 2 * 64, 1);
}

// round 8
// speedup vs baseline: 1.2327x; 1.1931x over previous
#include <cuda_runtime.h>
#include <cstdint>

#define BB   32
#define SS   1024
#define HH   256
#define G4   1024   // 4*H
#define H2   512    // 2*H

typedef unsigned long long ull;

// ---------------- f32x2 helpers (Blackwell packed fp32, 2 MAC/inst) -------
__device__ __forceinline__ ull ffma2(ull a, ull b, ull c)
{
    ull d;
    asm("fma.rn.f32x2 %0, %1, %2, %3;" : "=l"(d) : "l"(a), "l"(b), "l"(c));
    return d;
}
__device__ __forceinline__ ull pack_dup(float a)
{
    ull d;
    unsigned u = __float_as_uint(a);
    asm("mov.b64 %0, {%1, %1};" : "=l"(d) : "r"(u));
    return d;
}
__device__ __forceinline__ float2 unpack2(ull v)
{
    unsigned lo, hi;
    asm("mov.b64 {%0, %1}, %2;" : "=r"(lo), "=r"(hi) : "l"(v));
    return make_float2(__uint_as_float(lo), __uint_as_float(hi));
}

// ---------------- scoped release/acquire flag ops -------------------------
__device__ __forceinline__ void st_release_gpu(int* p, int v)
{
    asm volatile("st.release.gpu.global.u32 [%0], %1;" :: "l"(p), "r"(v) : "memory");
}
__device__ __forceinline__ int ld_acquire_gpu(const int* p)
{
    int v;
    asm volatile("ld.acquire.gpu.global.u32 %0, [%1];" : "=r"(v) : "l"(p) : "memory");
    return v;
}

// ------------------------- scratch (device globals; no allocs) -------------
// gates in recurrence layout: [s][unit_block(64)][b(32)][16]  (16 = gate*4+u)
__device__ float g_gates_f[(size_t)SS * BB * G4];   // 128 MB
__device__ float g_gates_b[(size_t)SS * BB * G4];   // 128 MB
__device__ float g_xout  [(size_t)SS * BB * H2];    //  64 MB (layer-0 output)
// replicated flags: [layer][dir][consumer(64)][producer(64)]
__device__ int   g_flags [2 * 2 * 64 * 64];
// h exchange: [dir][parity][b(32)][256]
__device__ float g_hx    [2 * 2 * 32 * 256];

// --------------------------------------------------------------------------
__global__ void zero_flags_k()
{
    int i = blockIdx.x * blockDim.x + threadIdx.x;
    if (i < 2 * 2 * 64 * 64) g_flags[i] = 0;
}

// --------------------------------------------------------------------------
// gates2[s][ub][b][g*4+u] = sum_k A_row(s,b)[k] * W[g*256+ub*4+u, k] + bih + bhh
// blockIdx.z selects forward (0) / backward (1) weight set + output buffer.
// Tiles 128x128, k-tile 16, 256 threads, 8x8 micro-tile, f32x2, pipelined LDG.
__global__ void __launch_bounds__(256) gates_gemm(
    const float* __restrict__ A,
    const float* __restrict__ Wf, const float* __restrict__ bihf, const float* __restrict__ bhhf,
    const float* __restrict__ Wb, const float* __restrict__ bihb, const float* __restrict__ bhhb,
    float* __restrict__ Cf, float* __restrict__ Cb,
    int K, int a_mode)
{
    __shared__ __align__(16) float As[16][132];
    __shared__ __align__(16) float Bs[16][132];

    const int z = blockIdx.z;
    const float* W   = z ? Wb   : Wf;
    const float* bih = z ? bihb : bihf;
    const float* bhh = z ? bhhb : bhhf;
    float* C2        = z ? Cb   : Cf;

    const int tid = threadIdx.x;
    const int tx = tid & 15;
    const int ty = tid >> 4;
    const int m0 = blockIdx.y * 128;
    const int n0 = blockIdx.x * 128;

    const int lr = tid >> 2;        // 0..63
    const int lc = (tid & 3) << 2;  // 0,4,8,12

    const float* arow0;
    const float* arow1;
    {
        int m  = m0 + lr;
        int m2 = m + 64;
        if (a_mode == 0) {
            int s = m >> 5, b = m & 31;
            arow0 = A + ((size_t)b * SS + s) * K;
            s = m2 >> 5; b = m2 & 31;
            arow1 = A + ((size_t)b * SS + s) * K;
        } else {
            arow0 = A + (size_t)m  * K;
            arow1 = A + (size_t)m2 * K;
        }
    }
    const float* wrow0 = W + (size_t)(n0 + lr)      * K;
    const float* wrow1 = W + (size_t)(n0 + lr + 64) * K;

    ull accp[8][4];
#pragma unroll
    for (int i = 0; i < 8; ++i)
#pragma unroll
        for (int j = 0; j < 4; ++j) accp[i][j] = 0ull;

    const int KT = K >> 4;

    // prologue load, tile 0
    float4 a0 = *(const float4*)(arow0 + lc);
    float4 a1 = *(const float4*)(arow1 + lc);
    float4 b0 = *(const float4*)(wrow0 + lc);
    float4 b1 = *(const float4*)(wrow1 + lc);

    for (int kt = 0; kt < KT; ++kt) {
        __syncthreads();
        As[lc + 0][lr] = a0.x; As[lc + 1][lr] = a0.y; As[lc + 2][lr] = a0.z; As[lc + 3][lr] = a0.w;
        As[lc + 0][lr + 64] = a1.x; As[lc + 1][lr + 64] = a1.y; As[lc + 2][lr + 64] = a1.z; As[lc + 3][lr + 64] = a1.w;
        Bs[lc + 0][lr] = b0.x; Bs[lc + 1][lr] = b0.y; Bs[lc + 2][lr] = b0.z; Bs[lc + 3][lr] = b0.w;
        Bs[lc + 0][lr + 64] = b1.x; Bs[lc + 1][lr + 64] = b1.y; Bs[lc + 2][lr + 64] = b1.z; Bs[lc + 3][lr + 64] = b1.w;
        __syncthreads();
        if (kt + 1 < KT) {            // in-flight during compute
            int k0 = (kt + 1) << 4;
            a0 = *(const float4*)(arow0 + k0 + lc);
            a1 = *(const float4*)(arow1 + k0 + lc);
            b0 = *(const float4*)(wrow0 + k0 + lc);
            b1 = *(const float4*)(wrow1 + k0 + lc);
        }
#pragma unroll
        for (int k = 0; k < 16; ++k) {
            float4 af0 = *(const float4*)&As[k][ty * 4];
            float4 af1 = *(const float4*)&As[k][64 + ty * 4];
            ulonglong2 bv0 = *(const ulonglong2*)&Bs[k][tx * 4];
            ulonglong2 bv1 = *(const ulonglong2*)&Bs[k][64 + tx * 4];
            ull bp[4] = {bv0.x, bv0.y, bv1.x, bv1.y};
            float a_[8] = {af0.x, af0.y, af0.z, af0.w, af1.x, af1.y, af1.z, af1.w};
#pragma unroll
            for (int i = 0; i < 8; ++i) {
                ull ad = pack_dup(a_[i]);
#pragma unroll
                for (int j = 0; j < 4; ++j)
                    accp[i][j] = ffma2(ad, bp[j], accp[i][j]);
            }
        }
    }

    // epilogue: bias add + store in recurrence layout
#pragma unroll
    for (int qi = 0; qi < 2; ++qi) {
#pragma unroll
        for (int i = 0; i < 4; ++i) {
            int m = m0 + qi * 64 + ty * 4 + i;
            int s = m >> 5, b = m & 31;
#pragma unroll
            for (int qj = 0; qj < 2; ++qj) {
                int n = n0 + qj * 64 + tx * 4;
                float2 p0 = unpack2(accp[qi * 4 + i][qj * 2 + 0]);
                float2 p1 = unpack2(accp[qi * 4 + i][qj * 2 + 1]);
                float4 v;
                v.x = p0.x + bih[n + 0] + bhh[n + 0];
                v.y = p0.y + bih[n + 1] + bhh[n + 1];
                v.z = p1.x + bih[n + 2] + bhh[n + 2];
                v.w = p1.y + bih[n + 3] + bhh[n + 3];
                int g  = n >> 8;
                int ub = (n & 255) >> 2;
                *(float4*)&C2[(((size_t)s * 64 + ub) * 32 + b) * 16 + g * 4] = v;
            }
        }
    }
}

// --------------------------------------------------------------------------
// Recurrence: 128 CTAs (blockIdx < 64: forward, else backward), 256 threads.
// Cross-CTA sync: replicated flags [dir][cons][prod] — consumer polls its own
// private 256B row with ld.acquire.gpu; producer fans out 64 st.release.gpu.
// h exchanged through compact parity buffer (coalesced STG.128 / __ldcg).
#define HS 260
#define GS 17

__device__ __forceinline__ float sigm_f(float x)
{
    float e = __expf(-x);
    return __fdividef(1.f, 1.f + e);
}
__device__ __forceinline__ float tanh_f(float x)
{
    float xc = fminf(fmaxf(x, -30.f), 30.f);
    float e = __expf(-2.f * xc);
    return __fdividef(1.f - e, 1.f + e);
}

__global__ void __launch_bounds__(256) lstm_recur(
    const float* __restrict__ gatesF2, const float* __restrict__ gatesB2,
    const float* __restrict__ WhhF, const float* __restrict__ WhhB,
    const float* __restrict__ mask,
    float* __restrict__ xout,
    float* __restrict__ hn_out, float* __restrict__ cn_out,
    int* __restrict__ flags,        // [dir][cons64][prod64]
    float* __restrict__ hx,         // [dir][parity][32][256]
    int out_bs)
{
    extern __shared__ __align__(16) float sm[];
    float* sh_w = sm;                       // 16 * HS
    float* sh_h = sm + 16 * HS;             // 32 * HS
    float* sh_g = sm + 16 * HS + 32 * HS;   // 32 * GS

    const int tid = threadIdx.x;
    const int dir = blockIdx.x >> 6;
    const int cb  = blockIdx.x & 63;
    const int u0  = cb * 4;

    const float* gates2 = dir ? gatesB2 : gatesF2;
    const float* Whh    = dir ? WhhB    : WhhF;
    int* fl_my   = flags + (dir * 64 + cb) * 64;   // row I poll
    int* fl_base = flags + dir * 64 * 64;          // rows I release into

    // Load the 16 Whh rows for this CTA's units: row r = gate*4 + u
    for (int idx = tid; idx < 16 * 64; idx += 256) {
        int r  = idx >> 6;
        int k4 = idx & 63;
        int grow = (r >> 2) * HH + u0 + (r & 3);
        float4 v = *(const float4*)(Whh + (size_t)grow * HH + k4 * 4);
        *(float4*)&sh_w[r * HS + k4 * 4] = v;
    }

    const int gb = tid >> 3;      // batch row this thread multiplies
    const int gi = tid & 7;
    const int r0 = gi, r1 = gi + 8;

    float4 c_state = make_float4(0.f, 0.f, 0.f, 0.f);   // tid<32: 4 units

    __syncthreads();

    for (int t = 0; t < SS; ++t) {
        const int s = dir ? (SS - 1 - t) : t;

        // x-gates: contiguous 2 KB per (step, CTA); issue early
        const float* gr = gates2 + ((size_t)s * 64 + cb) * 512 + gb * 16;
        float gx0 = __ldg(gr + r0);
        float gx1 = __ldg(gr + r1);
        float mt = 0.f;
        if (tid < 32) mt = __ldg(mask + tid * SS + s);

        if (t == 0) {
            for (int idx = tid; idx < 32 * HS; idx += 256) sh_h[idx] = 0.f;
            __syncthreads();
        } else {
            if (tid < 64) {
                const int* p = fl_my + tid;
                while (ld_acquire_gpu(p) < t) { __nanosleep(64); }
            }
            __syncthreads();
            // h(t-1) from parity slot, L2-coherent loads
            const float* src = hx + ((size_t)dir * 2 + ((t - 1) & 1)) * 32 * 256;
            for (int q = tid; q < 32 * 64; q += 256) {
                int b = q >> 6, k4 = q & 63;
                float4 v = __ldcg((const float4*)(src + b * 256 + k4 * 4));
                *(float4*)&sh_h[b * HS + k4 * 4] = v;
            }
            __syncthreads();
        }

        // gates_h = h_prev @ Whh_slice^T, f32x2 packed over k, 4 chains
        {
            const ulonglong2* hv  = (const ulonglong2*)&sh_h[gb * HS];
            const ulonglong2* w0v = (const ulonglong2*)&sh_w[r0 * HS];
            const ulonglong2* w1v = (const ulonglong2*)&sh_w[r1 * HS];
            ull a0a = 0, a0b = 0, a1a = 0, a1b = 0;
#pragma unroll 16
            for (int k2 = 0; k2 < 64; ++k2) {
                ulonglong2 h = hv[k2];
                ulonglong2 W0 = w0v[k2];
                ulonglong2 W1 = w1v[k2];
                a0a = ffma2(h.x, W0.x, a0a);
                a0b = ffma2(h.y, W0.y, a0b);
                a1a = ffma2(h.x, W1.x, a1a);
                a1b = ffma2(h.y, W1.y, a1b);
            }
            float2 u0a = unpack2(a0a), u0b = unpack2(a0b);
            float2 u1a = unpack2(a1a), u1b = unpack2(a1b);
            sh_g[gb * GS + r0] = gx0 + (u0a.x + u0a.y) + (u0b.x + u0b.y);
            sh_g[gb * GS + r1] = gx1 + (u1a.x + u1a.y) + (u1b.x + u1b.y);
        }
        __syncthreads();

        // cell: 32 threads, one batch each, 4 units
        if (tid < 32) {
            const float* gg = &sh_g[tid * GS];
            float4 hn4, cn4;
            float* hnp = &hn4.x;
            float* cnp = &cn4.x;
            float* csp = &c_state.x;
#pragma unroll
            for (int u = 0; u < 4; ++u) {
                float ig = sigm_f(gg[0  + u]);
                float fg = sigm_f(gg[4  + u]);
                float gv = tanh_f(gg[8  + u]);
                float og = sigm_f(gg[12 + u]);
                float cn = fg * csp[u] + ig * gv;
                float hn = og * tanh_f(cn);
                hn *= mt;            // + h0*(1-mt), h0 == 0
                cn *= mt;            // + c0*(1-mt), c0 == 0
                csp[u] = cn;
                hnp[u] = hn;
                cnp[u] = cn;
            }
            // exchange buffer (critical path)
            float* dst = hx + (((size_t)dir * 2 + (t & 1)) * 32 + tid) * 256 + u0;
            *(float4*)dst = hn4;
            // layer output (not on critical path)
            size_t orow = out_bs ? ((size_t)tid * SS + s)
                                 : ((size_t)s * BB + tid);
            *(float4*)&xout[orow * H2 + dir * HH + u0] = hn4;
            if (t == SS - 1) {
                *(float4*)&hn_out[tid * H2 + dir * HH + u0] = hn4;
                *(float4*)&cn_out[tid * H2 + dir * HH + u0] = cn4;
            }
        }
        __syncthreads();   // h stores happen-before the releases below
        if (tid < 64) {
            st_release_gpu(fl_base + tid * 64 + cb, t + 1);
        }
    }
}

// --------------------------------------------------------------------------
extern "C" void kernel_launch(void* const* d_in, const int* in_sizes, int n_in,
                              void* d_out, int out_size)
{
    const float* inputs  = (const float*)d_in[0];
    const float* mask    = (const float*)d_in[1];
    const float* l0f_Wih = (const float*)d_in[2];
    const float* l0f_Whh = (const float*)d_in[3];
    const float* l0f_bih = (const float*)d_in[4];
    const float* l0f_bhh = (const float*)d_in[5];
    const float* l0b_Wih = (const float*)d_in[6];
    const float* l0b_Whh = (const float*)d_in[7];
    const float* l0b_bih = (const float*)d_in[8];
    const float* l0b_bhh = (const float*)d_in[9];
    const float* l1f_Wih = (const float*)d_in[10];
    const float* l1f_Whh = (const float*)d_in[11];
    const float* l1f_bih = (const float*)d_in[12];
    const float* l1f_bhh = (const float*)d_in[13];
    const float* l1b_Wih = (const float*)d_in[14];
    const float* l1b_Whh = (const float*)d_in[15];
    const float* l1b_bih = (const float*)d_in[16];
    const float* l1b_bhh = (const float*)d_in[17];
    float* out = (float*)d_out;

    float *p_gf, *p_gb, *p_x, *p_hx;
    int *p_fl;
    cudaGetSymbolAddress((void**)&p_gf, g_gates_f);
    cudaGetSymbolAddress((void**)&p_gb, g_gates_b);
    cudaGetSymbolAddress((void**)&p_x,  g_xout);
    cudaGetSymbolAddress((void**)&p_fl, g_flags);
    cudaGetSymbolAddress((void**)&p_hx, g_hx);

    const int smem_rec = (16 * HS + 32 * HS + 32 * GS) * 4;   // 52096 B
    cudaFuncSetAttribute(lstm_recur, cudaFuncAttributeMaxDynamicSharedMemorySize, smem_rec);

    const size_t HN_OFF = (size_t)BB * SS * H2;       // 16777216
    const size_t CN_OFF = HN_OFF + 2 * (size_t)BB * H2;
    float* hn0 = out + HN_OFF;
    float* hn1 = out + HN_OFF + (size_t)BB * H2;
    float* cn0 = out + CN_OFF;
    float* cn1 = out + CN_OFF + (size_t)BB * H2;

    zero_flags_k<<<64, 256>>>();

    dim3 ggrid(G4 / 128, (SS * BB) / 128, 2);   // (8, 256, 2) fwd+bwd merged

    // ---- layer 0 : recurrence output in [S,B,2H] scratch ----
    gates_gemm<<<ggrid, 256>>>(inputs,
                               l0f_Wih, l0f_bih, l0f_bhh,
                               l0b_Wih, l0b_bih, l0b_bhh,
                               p_gf, p_gb, 256, 0);
    lstm_recur<<<128, 256, smem_rec>>>(p_gf, p_gb, l0f_Whh, l0b_Whh, mask,
                                       p_x, hn0, cn0, p_fl, p_hx, 0);

    // ---- layer 1 : recurrence writes final [B,S,2H] output directly ----
    gates_gemm<<<ggrid, 256>>>(p_x,
                               l1f_Wih, l1f_bih, l1f_bhh,
                               l1b_Wih, l1b_bih, l1b_bhh,
                               p_gf, p_gb, 512, 1);
    lstm_recur<<<128, 256, smem_rec>>>(p_gf, p_gb, l1f_Whh, l1b_Whh, mask,
                                       out, hn1, cn1, p_fl + 2 * 64 * 64, p_hx, 1);
}